// round 12
// baseline (speedup 1.0000x reference)
#include <cuda_runtime.h>
#include <cuda_fp16.h>
#include <math.h>
#include <stdint.h>

#define B_SZ 1024
#define L_SZ 110
#define D_SZ 512
#define WPAST 10
#define WFUT 10
#define M_TOT (B_SZ * L_SZ)   // 112640

// ---------------- device scratch (allocation-guard-safe) -------------------
__device__ float  g_att[(size_t)M_TOT * D_SZ];     // compact att rows
__device__ __half g_Ahi[(size_t)M_TOT * D_SZ];     // compact hi rows
__device__ __half g_Alo[(size_t)M_TOT * D_SZ];     // compact lo rows
__device__ __half g_Whi[D_SZ * D_SZ];
__device__ __half g_Wlo[D_SZ * D_SZ];
__device__ int    g_cbase[B_SZ + 1];               // exclusive prefix of len; [B]=Mc
__device__ int    g_rowmap[M_TOT];                 // compact row -> absolute row

__device__ __forceinline__ uint32_t smem_u32(const void* p) {
    uint32_t a;
    asm("{ .reg .u64 t; cvta.to.shared.u64 t, %1; cvt.u32.u64 %0, t; }"
        : "=r"(a) : "l"(p));
    return a;
}

#define LDSM4(d, addr) \
    asm volatile("ldmatrix.sync.aligned.m8n8.x4.shared.b16 {%0,%1,%2,%3}, [%4];" \
        : "=r"((d)[0]), "=r"((d)[1]), "=r"((d)[2]), "=r"((d)[3]) : "r"(addr))

#define MMA_16816(d, a, b) \
    asm volatile("mma.sync.aligned.m16n8k16.row.col.f32.f16.f16.f32 " \
        "{%0,%1,%2,%3},{%4,%5,%6,%7},{%8,%9},{%0,%1,%2,%3};" \
        : "+f"((d)[0]), "+f"((d)[1]), "+f"((d)[2]), "+f"((d)[3]) \
        : "r"((a)[0]), "r"((a)[1]), "r"((a)[2]), "r"((a)[3]), \
          "r"((b)[0]), "r"((b)[1]))

#define CP_ASYNC16(saddr, gptr) \
    asm volatile("cp.async.cg.shared.global [%0], [%1], 16;" \
                 :: "r"(saddr), "l"(gptr) : "memory")
#define CP_COMMIT() asm volatile("cp.async.commit_group;" ::: "memory")
#define CP_WAIT2()  asm volatile("cp.async.wait_group 2;" ::: "memory")
#define CP_WAIT1()  asm volatile("cp.async.wait_group 1;" ::: "memory")
#define CP_WAIT0()  asm volatile("cp.async.wait_group 0;" ::: "memory")

// ---------------------------------------------------------------------------
// Prefix scan of text_len (one block, 1024 threads, Hillis-Steele)
// ---------------------------------------------------------------------------
__global__ __launch_bounds__(1024) void scan_len(const int* __restrict__ tlen) {
    __shared__ int s[B_SZ];
    const int t = threadIdx.x;
    s[t] = tlen[t];
    __syncthreads();
    for (int off = 1; off < B_SZ; off <<= 1) {
        int v = (t >= off) ? s[t - off] : 0;
        __syncthreads();
        s[t] += v;
        __syncthreads();
    }
    if (t == 0) g_cbase[0] = 0;
    g_cbase[t + 1] = s[t];
}

__global__ __launch_bounds__(128) void fill_rowmap(const int* __restrict__ tlen) {
    const int b    = blockIdx.x;
    const int len  = tlen[b];
    const int base = g_cbase[b];
    for (int l = threadIdx.x; l < len; l += 128)
        g_rowmap[base + l] = b * L_SZ + l;
}

// ---------------------------------------------------------------------------
// Gathered fp16 split: only compact (live) rows; 2 float4 per thread.
// ---------------------------------------------------------------------------
__global__ __launch_bounds__(256) void split_A_compact(const float* __restrict__ src) {
    const int Mc = g_cbase[B_SZ];
    size_t i = (size_t)blockIdx.x * blockDim.x + threadIdx.x;   // 32B-pair index
    int mc = (int)(i >> 6);                                     // 64 pairs per row
    if (mc >= Mc) return;
    int q = (int)(i & 63) * 2;                                  // float4 idx in row
    const float4* srow = (const float4*)(src + (size_t)g_rowmap[mc] * D_SZ) + q;
#pragma unroll
    for (int t = 0; t < 2; t++) {
        float4 v = srow[t];
        __half h0 = __float2half_rn(v.x), h1 = __float2half_rn(v.y);
        __half h2 = __float2half_rn(v.z), h3 = __float2half_rn(v.w);
        __half l0 = __float2half_rn(v.x - __half2float(h0));
        __half l1 = __float2half_rn(v.y - __half2float(h1));
        __half l2 = __float2half_rn(v.z - __half2float(h2));
        __half l3 = __float2half_rn(v.w - __half2float(h3));
        size_t o = (size_t)mc * 256 + (q + t) * 2;              // half2 index
        ((__half2*)g_Ahi)[o + 0] = __halves2half2(h0, h1);
        ((__half2*)g_Ahi)[o + 1] = __halves2half2(h2, h3);
        ((__half2*)g_Alo)[o + 0] = __halves2half2(l0, l1);
        ((__half2*)g_Alo)[o + 1] = __halves2half2(l2, l3);
    }
}
__global__ __launch_bounds__(256) void split_W(const float* __restrict__ src) {
    size_t i = (size_t)blockIdx.x * blockDim.x + threadIdx.x;
    const size_t n4 = (size_t)D_SZ * D_SZ / 4;
    if (i >= n4) return;
    float4 v = ((const float4*)src)[i];
    __half h0 = __float2half_rn(v.x), h1 = __float2half_rn(v.y);
    __half h2 = __float2half_rn(v.z), h3 = __float2half_rn(v.w);
    __half l0 = __float2half_rn(v.x - __half2float(h0));
    __half l1 = __float2half_rn(v.y - __half2float(h1));
    __half l2 = __float2half_rn(v.z - __half2float(h2));
    __half l3 = __float2half_rn(v.w - __half2float(h3));
    ((__half2*)g_Whi)[i * 2 + 0] = __halves2half2(h0, h1);
    ((__half2*)g_Whi)[i * 2 + 1] = __halves2half2(h2, h3);
    ((__half2*)g_Wlo)[i * 2 + 0] = __halves2half2(l0, l1);
    ((__half2*)g_Wlo)[i * 2 + 1] = __halves2half2(l2, l3);
}

// ---------------------------------------------------------------------------
// HMMA GEMM over COMPACT rows: att_c[mc, n] = sum_k A_c[mc, k] * W[n, k]
// CTA 128x256, 8 warps of 64x64. K chunks of 32 halves, 80B smem row stride,
// cp.async TRIPLE buffer. 3 split-fp16 passes per k16 step.
// ---------------------------------------------------------------------------
#define KC 32
#define ROWB 80
#define A_T (128 * ROWB)             // 10240
#define W_T (256 * ROWB)             // 20480
#define OFF_AHI 0
#define OFF_ALO A_T
#define OFF_WHI (2 * A_T)
#define OFF_WLO (2 * A_T + W_T)
#define STAGE (2 * A_T + 2 * W_T)    // 61440
#define NSTAGE 3
#define GEMM_SMEM (NSTAGE * STAGE)   // 184320
#define NCHUNK (D_SZ / KC)           // 16

__global__ __launch_bounds__(256, 1) void edgeatt_gemm_hmma() {
    const int Mc = g_cbase[B_SZ];
    const int m0 = blockIdx.y * 128;
    if (m0 >= Mc) return;                       // dead tile

    extern __shared__ char smg[];
    const uint32_t sb = smem_u32(smg);
    const int tid  = threadIdx.x;
    const int wid  = tid >> 5;
    const int lane = tid & 31;
    const int wm = wid >> 2;                    // 0..1 -> m offset wm*64
    const int wn = wid & 3;                     // 0..3 -> n offset wn*64
    const int n0 = blockIdx.x * 256;

    float acc[4][8][4];
#pragma unroll
    for (int i = 0; i < 4; i++)
#pragma unroll
        for (int j = 0; j < 8; j++)
#pragma unroll
            for (int q = 0; q < 4; q++) acc[i][j][q] = 0.f;

    size_t aoff[2]; int asf[2];
#pragma unroll
    for (int i = 0; i < 2; i++) {
        int idx = tid + i * 256, row = idx >> 2, ch = idx & 3;
        aoff[i] = (size_t)(m0 + row) * D_SZ + ch * 8;
        asf[i]  = row * ROWB + ch * 16;
    }
    size_t woff[4]; int wsf[4];
#pragma unroll
    for (int i = 0; i < 4; i++) {
        int idx = tid + i * 256, row = idx >> 2, ch = idx & 3;
        woff[i] = (size_t)(n0 + row) * D_SZ + ch * 8;
        wsf[i]  = row * ROWB + ch * 16;
    }

    auto issue = [&](int c, int buf) {
        const uint32_t s0 = sb + buf * STAGE;
        const size_t ka = (size_t)c * KC;
#pragma unroll
        for (int i = 0; i < 2; i++) {
            CP_ASYNC16(s0 + OFF_AHI + asf[i], g_Ahi + aoff[i] + ka);
            CP_ASYNC16(s0 + OFF_ALO + asf[i], g_Alo + aoff[i] + ka);
        }
#pragma unroll
        for (int i = 0; i < 4; i++) {
            CP_ASYNC16(s0 + OFF_WHI + wsf[i], g_Whi + woff[i] + ka);
            CP_ASYNC16(s0 + OFF_WLO + wsf[i], g_Wlo + woff[i] + ka);
        }
        CP_COMMIT();
    };

    issue(0, 0);
    issue(1, 1);

    const int g = lane >> 3, r = lane & 7;
    const int arow = wm * 64 + ((g & 1) << 3) + r;
    const int brow = wn * 64 + ((g >> 1) << 3) + r;
    const int akc  = (g >> 1);
    const int bkc  = (g & 1);

    for (int c = 0; c < NCHUNK; c++) {
        const int buf = c % NSTAGE;
        if (c + 2 < NCHUNK) { issue(c + 2, (c + 2) % NSTAGE); CP_WAIT2(); }
        else if (c + 1 < NCHUNK) { CP_WAIT1(); }
        else { CP_WAIT0(); }
        __syncthreads();

        const uint32_t abase = sb + buf * STAGE;
#pragma unroll
        for (int ks = 0; ks < 2; ks++) {
            uint32_t ah[4][4], al[4][4], bh[4][4], bl[4][4];
#pragma unroll
            for (int mt = 0; mt < 4; mt++) {
                uint32_t ad = abase + OFF_AHI + (arow + mt * 16) * ROWB
                            + (ks * 2 + akc) * 16;
                LDSM4(ah[mt], ad);
                LDSM4(al[mt], ad + (OFF_ALO - OFF_AHI));
            }
#pragma unroll
            for (int bt = 0; bt < 4; bt++) {
                uint32_t bd = abase + OFF_WHI + (brow + bt * 16) * ROWB
                            + (ks * 2 + bkc) * 16;
                LDSM4(bh[bt], bd);
                LDSM4(bl[bt], bd + (OFF_WLO - OFF_WHI));
            }
#pragma unroll
            for (int mt = 0; mt < 4; mt++)
#pragma unroll
                for (int nt = 0; nt < 8; nt++) {
                    const int bt = nt >> 1, h = (nt & 1) * 2;
                    MMA_16816(acc[mt][nt], ah[mt], &bh[bt][h]);
                    MMA_16816(acc[mt][nt], ah[mt], &bl[bt][h]);
                    MMA_16816(acc[mt][nt], al[mt], &bh[bt][h]);
                }
        }
        __syncthreads();
    }

    const int er = lane >> 2, ec = (lane & 3) * 2;
#pragma unroll
    for (int mt = 0; mt < 4; mt++) {
        const int row = m0 + wm * 64 + mt * 16 + er;
#pragma unroll
        for (int nt = 0; nt < 8; nt++) {
            const int col = n0 + wn * 64 + nt * 8 + ec;
            if (row < Mc)
                *(float2*)&g_att[(size_t)row * D_SZ + col] =
                    make_float2(acc[mt][nt][0], acc[mt][nt][1]);
            if (row + 8 < Mc)
                *(float2*)&g_att[(size_t)(row + 8) * D_SZ + col] =
                    make_float2(acc[mt][nt][2], acc[mt][nt][3]);
        }
    }
}

// ---------------------------------------------------------------------------
// Band + softmax: one warp handles FOUR adjacent j rows.
// Value-multiplexed warp reduction: 4 dot sums in 6 shfls + 1 scatter shfl
// (vs 20 before) — cuts MIO pressure on the L1/shfl pipe.
// ---------------------------------------------------------------------------
#define NJ 4
#define UNION_W (WPAST + WFUT + NJ)   // 24

__global__ __launch_bounds__(256) void edgeatt_band_softmax(
    const float* __restrict__ nf,     // [B, L, 512]
    const int*   __restrict__ tlen,   // [B]
    float*       __restrict__ out)    // [B, L, 110]
{
    const int b    = blockIdx.y;
    const int warp = threadIdx.x >> 5;
    const int lane = threadIdx.x & 31;
    const int j0   = blockIdx.x * (8 * NJ) + warp * NJ;
    if (j0 >= L_SZ) return;

    const int len  = tlen[b];
    const int base = g_cbase[b];

    if (j0 >= len) {
#pragma unroll
        for (int r = 0; r < NJ; r++) {
            int j = j0 + r;
            if (j >= L_SZ) break;
            float* orow = out + ((size_t)b * L_SZ + j) * 110;
#pragma unroll
            for (int c0 = 0; c0 < 128; c0 += 32) {
                int c = c0 + lane;
                if (c < 110) orow[c] = 0.f;
            }
        }
        return;
    }

    float4 x[NJ][4];
#pragma unroll
    for (int r = 0; r < NJ; r++) {
        int j = min(j0 + r, L_SZ - 1);
        const float* xr = nf + ((size_t)b * L_SZ + j) * D_SZ;
#pragma unroll
        for (int q = 0; q < 4; q++)
            x[r][q] = *(const float4*)&xr[lane * 16 + q * 4];
    }

    const int lo = j0 - WPAST;
    float sc0 = 0.f, sc1 = 0.f, sc2 = 0.f, sc3 = 0.f;
    const bool up16 = (lane & 16) != 0;
    const bool up8  = (lane & 8)  != 0;

#pragma unroll 1
    for (int wi = 0; wi < UNION_W; wi++) {
        int l = lo + wi;                       // warp-uniform
        if (l < 0 || l >= len) continue;
        const float* ar = g_att + ((size_t)(base + l)) * D_SZ;
        float s0 = 0.f, s1 = 0.f, s2 = 0.f, s3 = 0.f;
#pragma unroll
        for (int q = 0; q < 4; q++) {
            float4 av = *(const float4*)&ar[lane * 16 + q * 4];
            s0 = fmaf(av.x, x[0][q].x, s0); s1 = fmaf(av.x, x[1][q].x, s1);
            s2 = fmaf(av.x, x[2][q].x, s2); s3 = fmaf(av.x, x[3][q].x, s3);
            s0 = fmaf(av.y, x[0][q].y, s0); s1 = fmaf(av.y, x[1][q].y, s1);
            s2 = fmaf(av.y, x[2][q].y, s2); s3 = fmaf(av.y, x[3][q].y, s3);
            s0 = fmaf(av.z, x[0][q].z, s0); s1 = fmaf(av.z, x[1][q].z, s1);
            s2 = fmaf(av.z, x[2][q].z, s2); s3 = fmaf(av.z, x[3][q].z, s3);
            s0 = fmaf(av.w, x[0][q].w, s0); s1 = fmaf(av.w, x[1][q].w, s1);
            s2 = fmaf(av.w, x[2][q].w, s2); s3 = fmaf(av.w, x[3][q].w, s3);
        }
        // value-multiplexed reduction:
        // level 16: fold (s0,s1) with (s2,s3) across half-warps
        float xa = up16 ? s0 : s2;             // value sent to partner
        float xb = up16 ? s1 : s3;
        float ra = __shfl_xor_sync(0xffffffffu, xa, 16);
        float rb = __shfl_xor_sync(0xffffffffu, xb, 16);
        float u = (up16 ? s2 : s0) + ra;       // low half: s0 over 32; high: s2
        float v = (up16 ? s3 : s1) + rb;       // low half: s1; high: s3
        // level 8: fold u with v
        float y  = up8 ? u : v;
        float ry = __shfl_xor_sync(0xffffffffu, y, 8);
        float red = (up8 ? v : u) + ry;        // group lane>>3 holds s_{lane>>3}
        // levels 4,2,1: plain butterfly; sum replicated within each 8-lane group
#pragma unroll
        for (int off = 4; off > 0; off >>= 1)
            red += __shfl_xor_sync(0xffffffffu, red, off);
        // scatter: lane (wi - r) needs group r's sum
        int rr = wi - lane;
        float val = __shfl_sync(0xffffffffu, red, (rr & 3) << 3);
        if (lane == wi)          sc0 = val;
        else if (lane == wi - 1) sc1 = val;
        else if (lane == wi - 2) sc2 = val;
        else if (lane == wi - 3) sc3 = val;
    }

    float scv[NJ] = {sc0, sc1, sc2, sc3};
    float pr[NJ];
#pragma unroll
    for (int r = 0; r < NJ; r++) {
        int  j  = j0 + r;
        int  lw = lo + r + lane;
        bool va = (lane < 21) && (lw >= 0) && (lw < len) && (j < len) && (j < L_SZ);
        float v = va ? scv[r] : -1e30f;
        float m = v;
#pragma unroll
        for (int off = 16; off > 0; off >>= 1)
            m = fmaxf(m, __shfl_xor_sync(0xffffffffu, m, off));
        float p = va ? expf(v - m) : 0.f;
        float t = p;
#pragma unroll
        for (int off = 16; off > 0; off >>= 1)
            t += __shfl_xor_sync(0xffffffffu, t, off);
        pr[r] = va ? (p / t) : 0.f;
    }

#pragma unroll
    for (int r = 0; r < NJ; r++) {
        int j = j0 + r;
        if (j >= L_SZ) break;
        float* orow = out + ((size_t)b * L_SZ + j) * 110;
#pragma unroll
        for (int c0 = 0; c0 < 128; c0 += 32) {
            int c  = c0 + lane;
            int w  = c - lo - r;
            int si = (w >= 0 && w < 32) ? w : 31;
            float val = __shfl_sync(0xffffffffu, pr[r], si);
            if (w < 0 || w >= 32) val = 0.f;
            if (c < 110) orow[c] = val;
        }
    }
}

// ---------------------------------------------------------------------------
extern "C" void kernel_launch(void* const* d_in, const int* in_sizes, int n_in,
                              void* d_out, int out_size)
{
    const float* nf   = (const float*)d_in[0];
    const float* W    = (const float*)d_in[1];
    const int*   tlen = (const int*)d_in[2];
    float* out = (float*)d_out;

    static int attr_done = 0;
    if (!attr_done) {
        cudaFuncSetAttribute(edgeatt_gemm_hmma,
                             cudaFuncAttributeMaxDynamicSharedMemorySize, GEMM_SMEM);
        attr_done = 1;
    }

    scan_len<<<1, 1024>>>(tlen);
    fill_rowmap<<<B_SZ, 128>>>(tlen);
    split_W<<<(D_SZ * D_SZ / 4 + 255) / 256, 256>>>(W);
    split_A_compact<<<((size_t)M_TOT * 64 + 255) / 256, 256>>>(nf);

    dim3 gg(D_SZ / 256, M_TOT / 128);    // (2, 880); dead tiles exit on Mc
    edgeatt_gemm_hmma<<<gg, 256, GEMM_SMEM>>>();

    dim3 gb((L_SZ + 8 * NJ - 1) / (8 * NJ), B_SZ);   // (4, 1024)
    edgeatt_band_softmax<<<gb, 256>>>(nf, tlen, out);
}

// round 16
// speedup vs baseline: 1.1049x; 1.1049x over previous
#include <cuda_runtime.h>
#include <cuda_fp16.h>
#include <math.h>
#include <stdint.h>

#define B_SZ 1024
#define L_SZ 110
#define D_SZ 512
#define WPAST 10
#define WFUT 10
#define M_TOT (B_SZ * L_SZ)   // 112640

// ---------------- device scratch (allocation-guard-safe) -------------------
__device__ float  g_att[(size_t)M_TOT * D_SZ];     // compact att rows
__device__ __half g_Whi[D_SZ * D_SZ];
__device__ __half g_Wlo[D_SZ * D_SZ];
__device__ int    g_cbase[B_SZ + 1];               // exclusive prefix of len; [B]=Mc
__device__ int    g_rowmap[M_TOT];                 // compact row -> absolute row

__device__ __forceinline__ uint32_t smem_u32(const void* p) {
    uint32_t a;
    asm("{ .reg .u64 t; cvta.to.shared.u64 t, %1; cvt.u32.u64 %0, t; }"
        : "=r"(a) : "l"(p));
    return a;
}

#define LDSM4(d, addr) \
    asm volatile("ldmatrix.sync.aligned.m8n8.x4.shared.b16 {%0,%1,%2,%3}, [%4];" \
        : "=r"((d)[0]), "=r"((d)[1]), "=r"((d)[2]), "=r"((d)[3]) : "r"(addr))

#define MMA_16816(d, a, b) \
    asm volatile("mma.sync.aligned.m16n8k16.row.col.f32.f16.f16.f32 " \
        "{%0,%1,%2,%3},{%4,%5,%6,%7},{%8,%9},{%0,%1,%2,%3};" \
        : "+f"((d)[0]), "+f"((d)[1]), "+f"((d)[2]), "+f"((d)[3]) \
        : "r"((a)[0]), "r"((a)[1]), "r"((a)[2]), "r"((a)[3]), \
          "r"((b)[0]), "r"((b)[1]))

#define CP_ASYNC16(saddr, gptr) \
    asm volatile("cp.async.cg.shared.global [%0], [%1], 16;" \
                 :: "r"(saddr), "l"(gptr) : "memory")
#define CP_COMMIT() asm volatile("cp.async.commit_group;" ::: "memory")
#define CP_WAIT1()  asm volatile("cp.async.wait_group 1;" ::: "memory")
#define CP_WAIT0()  asm volatile("cp.async.wait_group 0;" ::: "memory")

// ---------------------------------------------------------------------------
// Prefix scan of text_len (one block, 1024 threads, Hillis-Steele)
// ---------------------------------------------------------------------------
__global__ __launch_bounds__(1024) void scan_len(const int* __restrict__ tlen) {
    __shared__ int s[B_SZ];
    const int t = threadIdx.x;
    s[t] = tlen[t];
    __syncthreads();
    for (int off = 1; off < B_SZ; off <<= 1) {
        int v = (t >= off) ? s[t - off] : 0;
        __syncthreads();
        s[t] += v;
        __syncthreads();
    }
    if (t == 0) g_cbase[0] = 0;
    g_cbase[t + 1] = s[t];
}

__global__ __launch_bounds__(128) void fill_rowmap(const int* __restrict__ tlen) {
    const int b    = blockIdx.x;
    const int len  = tlen[b];
    const int base = g_cbase[b];
    for (int l = threadIdx.x; l < len; l += 128)
        g_rowmap[base + l] = b * L_SZ + l;
}

// ---------------------------------------------------------------------------
// fp16 hi/lo split of W only (A is split in-GEMM now)
// ---------------------------------------------------------------------------
__global__ __launch_bounds__(256) void split_W(const float* __restrict__ src) {
    size_t i = (size_t)blockIdx.x * blockDim.x + threadIdx.x;
    const size_t n4 = (size_t)D_SZ * D_SZ / 4;
    if (i >= n4) return;
    float4 v = ((const float4*)src)[i];
    __half h0 = __float2half_rn(v.x), h1 = __float2half_rn(v.y);
    __half h2 = __float2half_rn(v.z), h3 = __float2half_rn(v.w);
    __half l0 = __float2half_rn(v.x - __half2float(h0));
    __half l1 = __float2half_rn(v.y - __half2float(h1));
    __half l2 = __float2half_rn(v.z - __half2float(h2));
    __half l3 = __float2half_rn(v.w - __half2float(h3));
    ((__half2*)g_Whi)[i * 2 + 0] = __halves2half2(h0, h1);
    ((__half2*)g_Whi)[i * 2 + 1] = __halves2half2(h2, h3);
    ((__half2*)g_Wlo)[i * 2 + 0] = __halves2half2(l0, l1);
    ((__half2*)g_Wlo)[i * 2 + 1] = __halves2half2(l2, l3);
}

// ---------------------------------------------------------------------------
// HMMA GEMM over COMPACT rows: att_c[mc, n] = sum_k nf[rowmap[mc], k] * W[n, k]
// CTA 128x256, 8 warps of 64x64.  K chunks of 32, 80B smem row stride,
// double buffer.  W: cp.async (pre-split halves).  A: LDG fp32 (prefetched one
// chunk ahead) -> in-register hi/lo split -> STS halves.  3 passes per k16.
// ---------------------------------------------------------------------------
#define KC 32
#define ROWB 80
#define A_T (128 * ROWB)             // 10240
#define W_T (256 * ROWB)             // 20480
#define OFF_AHI 0
#define OFF_ALO A_T
#define OFF_WHI (2 * A_T)
#define OFF_WLO (2 * A_T + W_T)
#define STAGE (2 * A_T + 2 * W_T)    // 61440
#define GEMM_SMEM (2 * STAGE)        // 122880
#define NCHUNK (D_SZ / KC)           // 16

__global__ __launch_bounds__(256, 1) void edgeatt_gemm_hmma(
    const float* __restrict__ nf)
{
    const int Mc = g_cbase[B_SZ];
    const int m0 = blockIdx.y * 128;
    if (m0 >= Mc) return;                       // dead tile

    extern __shared__ char smg[];
    const uint32_t sb = smem_u32(smg);
    const int tid  = threadIdx.x;
    const int wid  = tid >> 5;
    const int lane = tid & 31;
    const int wm = wid >> 2;                    // 0..1 -> m offset wm*64
    const int wn = wid & 3;                     // 0..3 -> n offset wn*64
    const int n0 = blockIdx.x * 256;

    float acc[4][8][4];
#pragma unroll
    for (int i = 0; i < 4; i++)
#pragma unroll
        for (int j = 0; j < 8; j++)
#pragma unroll
            for (int q = 0; q < 4; q++) acc[i][j][q] = 0.f;

    // A fp32 mapping: 1024 float4-chunks (128 rows x 8), 4 per thread
    size_t aoff[4]; int asf[4];
#pragma unroll
    for (int i = 0; i < 4; i++) {
        int idx = tid + i * 256, row = idx >> 3, ch = idx & 7;
        aoff[i] = (size_t)g_rowmap[min(m0 + row, Mc - 1)] * D_SZ + ch * 4;
        asf[i]  = row * ROWB + ch * 8;          // 4 halves = 8 bytes
    }
    // W halves mapping: 1024 16B-chunks (256 rows x 4), 4 per thread
    size_t woff[4]; int wsf[4];
#pragma unroll
    for (int i = 0; i < 4; i++) {
        int idx = tid + i * 256, row = idx >> 2, ch = idx & 3;
        woff[i] = (size_t)(n0 + row) * D_SZ + ch * 8;
        wsf[i]  = row * ROWB + ch * 16;
    }

    auto issueW = [&](int c, int buf) {
        const uint32_t s0 = sb + buf * STAGE;
        const size_t ka = (size_t)c * KC;
#pragma unroll
        for (int i = 0; i < 4; i++) {
            CP_ASYNC16(s0 + OFF_WHI + wsf[i], g_Whi + woff[i] + ka);
            CP_ASYNC16(s0 + OFF_WLO + wsf[i], g_Wlo + woff[i] + ka);
        }
        CP_COMMIT();
    };
    float4 vA[4];
    auto ldA = [&](int c) {
        const size_t ka = (size_t)c * KC;
#pragma unroll
        for (int i = 0; i < 4; i++)
            vA[i] = *(const float4*)(nf + aoff[i] + ka);
    };
    auto stA = [&](int buf) {
        char* sp = smg + buf * STAGE;
#pragma unroll
        for (int i = 0; i < 4; i++) {
            float4 v = vA[i];
            __half h0 = __float2half_rn(v.x), h1 = __float2half_rn(v.y);
            __half h2 = __float2half_rn(v.z), h3 = __float2half_rn(v.w);
            __half l0 = __float2half_rn(v.x - __half2float(h0));
            __half l1 = __float2half_rn(v.y - __half2float(h1));
            __half l2 = __float2half_rn(v.z - __half2float(h2));
            __half l3 = __float2half_rn(v.w - __half2float(h3));
            __half2 hv[2] = { __halves2half2(h0, h1), __halves2half2(h2, h3) };
            __half2 lv[2] = { __halves2half2(l0, l1), __halves2half2(l2, l3) };
            *(uint2*)(sp + OFF_AHI + asf[i]) = *(uint2*)hv;
            *(uint2*)(sp + OFF_ALO + asf[i]) = *(uint2*)lv;
        }
    };

    // prologue: A chunk0 -> buf0, W chunk0 -> buf0 (group 0)
    ldA(0);
    issueW(0, 0);
    stA(0);

    const int g = lane >> 3, r = lane & 7;
    const int arow = wm * 64 + ((g & 1) << 3) + r;
    const int brow = wn * 64 + ((g >> 1) << 3) + r;
    const int akc  = (g >> 1);
    const int bkc  = (g & 1);

    for (int c = 0; c < NCHUNK; c++) {
        const int buf = c & 1;
        if (c + 1 < NCHUNK) {
            ldA(c + 1);                          // LDG latency hidden by compute
            issueW(c + 1, buf ^ 1);
            CP_WAIT1();                          // W chunk c complete
        } else {
            CP_WAIT0();
        }
        __syncthreads();                         // smem (A STS + W async) visible

        const uint32_t abase = sb + buf * STAGE;
#pragma unroll
        for (int ks = 0; ks < 2; ks++) {
            uint32_t ah[4][4], al[4][4], bh[4][4], bl[4][4];
#pragma unroll
            for (int mt = 0; mt < 4; mt++) {
                uint32_t ad = abase + OFF_AHI + (arow + mt * 16) * ROWB
                            + (ks * 2 + akc) * 16;
                LDSM4(ah[mt], ad);
                LDSM4(al[mt], ad + (OFF_ALO - OFF_AHI));
            }
#pragma unroll
            for (int bt = 0; bt < 4; bt++) {
                uint32_t bd = abase + OFF_WHI + (brow + bt * 16) * ROWB
                            + (ks * 2 + bkc) * 16;
                LDSM4(bh[bt], bd);
                LDSM4(bl[bt], bd + (OFF_WLO - OFF_WHI));
            }
#pragma unroll
            for (int mt = 0; mt < 4; mt++)
#pragma unroll
                for (int nt = 0; nt < 8; nt++) {
                    const int bt = nt >> 1, h = (nt & 1) * 2;
                    MMA_16816(acc[mt][nt], ah[mt], &bh[bt][h]);
                    MMA_16816(acc[mt][nt], ah[mt], &bl[bt][h]);
                    MMA_16816(acc[mt][nt], al[mt], &bh[bt][h]);
                }
        }

        if (c + 1 < NCHUNK)
            stA(buf ^ 1);                        // buf^1 A free since pre-compute sync
        __syncthreads();
    }

    // epilogue: compact-row store, predicated on Mc
    const int er = lane >> 2, ec = (lane & 3) * 2;
#pragma unroll
    for (int mt = 0; mt < 4; mt++) {
        const int row = m0 + wm * 64 + mt * 16 + er;
#pragma unroll
        for (int nt = 0; nt < 8; nt++) {
            const int col = n0 + wn * 64 + nt * 8 + ec;
            if (row < Mc)
                *(float2*)&g_att[(size_t)row * D_SZ + col] =
                    make_float2(acc[mt][nt][0], acc[mt][nt][1]);
            if (row + 8 < Mc)
                *(float2*)&g_att[(size_t)(row + 8) * D_SZ + col] =
                    make_float2(acc[mt][nt][2], acc[mt][nt][3]);
        }
    }
}

// ---------------------------------------------------------------------------
// Band + softmax: one warp handles FOUR adjacent j rows (R11 version).
// ---------------------------------------------------------------------------
#define NJ 4
#define UNION_W (WPAST + WFUT + NJ)   // 24

__global__ __launch_bounds__(256) void edgeatt_band_softmax(
    const float* __restrict__ nf,     // [B, L, 512]
    const int*   __restrict__ tlen,   // [B]
    float*       __restrict__ out)    // [B, L, 110]
{
    const int b    = blockIdx.y;
    const int warp = threadIdx.x >> 5;
    const int lane = threadIdx.x & 31;
    const int j0   = blockIdx.x * (8 * NJ) + warp * NJ;
    if (j0 >= L_SZ) return;

    const int len  = tlen[b];
    const int base = g_cbase[b];

    if (j0 >= len) {
#pragma unroll
        for (int r = 0; r < NJ; r++) {
            int j = j0 + r;
            if (j >= L_SZ) break;
            float* orow = out + ((size_t)b * L_SZ + j) * 110;
#pragma unroll
            for (int c0 = 0; c0 < 128; c0 += 32) {
                int c = c0 + lane;
                if (c < 110) orow[c] = 0.f;
            }
        }
        return;
    }

    float4 x[NJ][4];
#pragma unroll
    for (int r = 0; r < NJ; r++) {
        int j = min(j0 + r, L_SZ - 1);
        const float* xr = nf + ((size_t)b * L_SZ + j) * D_SZ;
#pragma unroll
        for (int q = 0; q < 4; q++)
            x[r][q] = *(const float4*)&xr[lane * 16 + q * 4];
    }

    const int lo = j0 - WPAST;
    float sc[NJ] = {0.f, 0.f, 0.f, 0.f};

#pragma unroll 1
    for (int wi = 0; wi < UNION_W; wi++) {
        int l = lo + wi;
        if (l < 0 || l >= len) continue;
        const float* ar = g_att + ((size_t)(base + l)) * D_SZ;
        float s0 = 0.f, s1 = 0.f, s2 = 0.f, s3 = 0.f;
#pragma unroll
        for (int q = 0; q < 4; q++) {
            float4 av = *(const float4*)&ar[lane * 16 + q * 4];
            s0 = fmaf(av.x, x[0][q].x, s0); s1 = fmaf(av.x, x[1][q].x, s1);
            s2 = fmaf(av.x, x[2][q].x, s2); s3 = fmaf(av.x, x[3][q].x, s3);
            s0 = fmaf(av.y, x[0][q].y, s0); s1 = fmaf(av.y, x[1][q].y, s1);
            s2 = fmaf(av.y, x[2][q].y, s2); s3 = fmaf(av.y, x[3][q].y, s3);
            s0 = fmaf(av.z, x[0][q].z, s0); s1 = fmaf(av.z, x[1][q].z, s1);
            s2 = fmaf(av.z, x[2][q].z, s2); s3 = fmaf(av.z, x[3][q].z, s3);
            s0 = fmaf(av.w, x[0][q].w, s0); s1 = fmaf(av.w, x[1][q].w, s1);
            s2 = fmaf(av.w, x[2][q].w, s2); s3 = fmaf(av.w, x[3][q].w, s3);
        }
#pragma unroll
        for (int off = 16; off > 0; off >>= 1) {
            s0 += __shfl_xor_sync(0xffffffffu, s0, off);
            s1 += __shfl_xor_sync(0xffffffffu, s1, off);
            s2 += __shfl_xor_sync(0xffffffffu, s2, off);
            s3 += __shfl_xor_sync(0xffffffffu, s3, off);
        }
        if (lane == wi)     sc[0] = s0;
        if (lane == wi - 1) sc[1] = s1;
        if (lane == wi - 2) sc[2] = s2;
        if (lane == wi - 3) sc[3] = s3;
    }

    float pr[NJ];
#pragma unroll
    for (int r = 0; r < NJ; r++) {
        int  j  = j0 + r;
        int  lw = lo + r + lane;
        bool va = (lane < 21) && (lw >= 0) && (lw < len) && (j < len) && (j < L_SZ);
        float v = va ? sc[r] : -1e30f;
        float m = v;
#pragma unroll
        for (int off = 16; off > 0; off >>= 1)
            m = fmaxf(m, __shfl_xor_sync(0xffffffffu, m, off));
        float p = va ? expf(v - m) : 0.f;
        float t = p;
#pragma unroll
        for (int off = 16; off > 0; off >>= 1)
            t += __shfl_xor_sync(0xffffffffu, t, off);
        pr[r] = va ? (p / t) : 0.f;
    }

#pragma unroll
    for (int r = 0; r < NJ; r++) {
        int j = j0 + r;
        if (j >= L_SZ) break;
        float* orow = out + ((size_t)b * L_SZ + j) * 110;
#pragma unroll
        for (int c0 = 0; c0 < 128; c0 += 32) {
            int c  = c0 + lane;
            int w  = c - lo - r;
            int si = (w >= 0 && w < 32) ? w : 31;
            float val = __shfl_sync(0xffffffffu, pr[r], si);
            if (w < 0 || w >= 32) val = 0.f;
            if (c < 110) orow[c] = val;
        }
    }
}

// ---------------------------------------------------------------------------
extern "C" void kernel_launch(void* const* d_in, const int* in_sizes, int n_in,
                              void* d_out, int out_size)
{
    const float* nf   = (const float*)d_in[0];
    const float* W    = (const float*)d_in[1];
    const int*   tlen = (const int*)d_in[2];
    float* out = (float*)d_out;

    static int attr_done = 0;
    if (!attr_done) {
        cudaFuncSetAttribute(edgeatt_gemm_hmma,
                             cudaFuncAttributeMaxDynamicSharedMemorySize, GEMM_SMEM);
        attr_done = 1;
    }

    scan_len<<<1, 1024>>>(tlen);
    fill_rowmap<<<B_SZ, 128>>>(tlen);
    split_W<<<(D_SZ * D_SZ / 4 + 255) / 256, 256>>>(W);

    dim3 gg(D_SZ / 256, M_TOT / 128);    // (2, 880); dead tiles exit on Mc
    edgeatt_gemm_hmma<<<gg, 256, GEMM_SMEM>>>(nf);

    dim3 gb((L_SZ + 8 * NJ - 1) / (8 * NJ), B_SZ);   // (4, 1024)
    edgeatt_band_softmax<<<gb, 256>>>(nf, tlen, out);
}

// round 17
// speedup vs baseline: 1.1495x; 1.0404x over previous
#include <cuda_runtime.h>
#include <cuda_fp16.h>
#include <math.h>
#include <stdint.h>

#define B_SZ 1024
#define L_SZ 110
#define D_SZ 512
#define WPAST 10
#define WFUT 10
#define M_TOT (B_SZ * L_SZ)   // 112640

// ---------------- device scratch (allocation-guard-safe) -------------------
__device__ float  g_att[(size_t)M_TOT * D_SZ];     // compact att rows
__device__ __half g_Whi[D_SZ * D_SZ];
__device__ __half g_Wlo[D_SZ * D_SZ];
__device__ int    g_cbase[B_SZ + 1];               // exclusive prefix of len; [B]=Mc
__device__ int    g_rowmap[M_TOT];                 // compact row -> absolute row

__device__ __forceinline__ uint32_t smem_u32(const void* p) {
    uint32_t a;
    asm("{ .reg .u64 t; cvta.to.shared.u64 t, %1; cvt.u32.u64 %0, t; }"
        : "=r"(a) : "l"(p));
    return a;
}

#define LDSM4(d, addr) \
    asm volatile("ldmatrix.sync.aligned.m8n8.x4.shared.b16 {%0,%1,%2,%3}, [%4];" \
        : "=r"((d)[0]), "=r"((d)[1]), "=r"((d)[2]), "=r"((d)[3]) : "r"(addr))

#define MMA_16816(d, a, b) \
    asm volatile("mma.sync.aligned.m16n8k16.row.col.f32.f16.f16.f32 " \
        "{%0,%1,%2,%3},{%4,%5,%6,%7},{%8,%9},{%0,%1,%2,%3};" \
        : "+f"((d)[0]), "+f"((d)[1]), "+f"((d)[2]), "+f"((d)[3]) \
        : "r"((a)[0]), "r"((a)[1]), "r"((a)[2]), "r"((a)[3]), \
          "r"((b)[0]), "r"((b)[1]))

#define CP_ASYNC16(saddr, gptr) \
    asm volatile("cp.async.cg.shared.global [%0], [%1], 16;" \
                 :: "r"(saddr), "l"(gptr) : "memory")
#define CP_COMMIT() asm volatile("cp.async.commit_group;" ::: "memory")
#define CP_WAIT1()  asm volatile("cp.async.wait_group 1;" ::: "memory")
#define CP_WAIT0()  asm volatile("cp.async.wait_group 0;" ::: "memory")

// ---------------------------------------------------------------------------
// Prefix scan of text_len (one block, 1024 threads, Hillis-Steele)
// ---------------------------------------------------------------------------
__global__ __launch_bounds__(1024) void scan_len(const int* __restrict__ tlen) {
    __shared__ int s[B_SZ];
    const int t = threadIdx.x;
    s[t] = tlen[t];
    __syncthreads();
    for (int off = 1; off < B_SZ; off <<= 1) {
        int v = (t >= off) ? s[t - off] : 0;
        __syncthreads();
        s[t] += v;
        __syncthreads();
    }
    if (t == 0) g_cbase[0] = 0;
    g_cbase[t + 1] = s[t];
}

__global__ __launch_bounds__(128) void fill_rowmap(const int* __restrict__ tlen) {
    const int b    = blockIdx.x;
    const int len  = tlen[b];
    const int base = g_cbase[b];
    for (int l = threadIdx.x; l < len; l += 128)
        g_rowmap[base + l] = b * L_SZ + l;
}

// ---------------------------------------------------------------------------
// fp16 hi/lo split of W only (A is split in-GEMM)
// ---------------------------------------------------------------------------
__global__ __launch_bounds__(256) void split_W(const float* __restrict__ src) {
    size_t i = (size_t)blockIdx.x * blockDim.x + threadIdx.x;
    const size_t n4 = (size_t)D_SZ * D_SZ / 4;
    if (i >= n4) return;
    float4 v = ((const float4*)src)[i];
    __half h0 = __float2half_rn(v.x), h1 = __float2half_rn(v.y);
    __half h2 = __float2half_rn(v.z), h3 = __float2half_rn(v.w);
    __half l0 = __float2half_rn(v.x - __half2float(h0));
    __half l1 = __float2half_rn(v.y - __half2float(h1));
    __half l2 = __float2half_rn(v.z - __half2float(h2));
    __half l3 = __float2half_rn(v.w - __half2float(h3));
    ((__half2*)g_Whi)[i * 2 + 0] = __halves2half2(h0, h1);
    ((__half2*)g_Whi)[i * 2 + 1] = __halves2half2(h2, h3);
    ((__half2*)g_Wlo)[i * 2 + 0] = __halves2half2(l0, l1);
    ((__half2*)g_Wlo)[i * 2 + 1] = __halves2half2(l2, l3);
}

// ---------------------------------------------------------------------------
// HMMA GEMM over COMPACT rows: att_c[mc, n] = sum_k nf[rowmap[mc], k] * W[n, k]
// CTA 128x256, 512 threads = 16 warps of 32x64 (wm 0..3, wn 0..3).
// K chunks of 32, 80B smem row stride, double buffer.
// W: cp.async (pre-split halves). A: LDG fp32 -> in-register split -> STS.
// ---------------------------------------------------------------------------
#define KC 32
#define ROWB 80
#define A_T (128 * ROWB)             // 10240
#define W_T (256 * ROWB)             // 20480
#define OFF_AHI 0
#define OFF_ALO A_T
#define OFF_WHI (2 * A_T)
#define OFF_WLO (2 * A_T + W_T)
#define STAGE (2 * A_T + 2 * W_T)    // 61440
#define GEMM_SMEM (2 * STAGE)        // 122880
#define NCHUNK (D_SZ / KC)           // 16
#define GT 512

__global__ __launch_bounds__(GT, 1) void edgeatt_gemm_hmma(
    const float* __restrict__ nf)
{
    const int Mc = g_cbase[B_SZ];
    const int m0 = blockIdx.y * 128;
    if (m0 >= Mc) return;                       // dead tile

    extern __shared__ char smg[];
    const uint32_t sb = smem_u32(smg);
    const int tid  = threadIdx.x;
    const int wid  = tid >> 5;
    const int lane = tid & 31;
    const int wm = wid >> 2;                    // 0..3 -> m offset wm*32
    const int wn = wid & 3;                     // 0..3 -> n offset wn*64
    const int n0 = blockIdx.x * 256;

    float acc[2][8][4];
#pragma unroll
    for (int i = 0; i < 2; i++)
#pragma unroll
        for (int j = 0; j < 8; j++)
#pragma unroll
            for (int q = 0; q < 4; q++) acc[i][j][q] = 0.f;

    // A fp32 mapping: 1024 float4-chunks (128 rows x 8), 2 per thread
    size_t aoff[2]; int asf[2];
#pragma unroll
    for (int i = 0; i < 2; i++) {
        int idx = tid + i * GT, row = idx >> 3, ch = idx & 7;
        aoff[i] = (size_t)g_rowmap[min(m0 + row, Mc - 1)] * D_SZ + ch * 4;
        asf[i]  = row * ROWB + ch * 8;          // 4 halves = 8 bytes
    }
    // W halves mapping: 1024 16B-chunks (256 rows x 4), 2 per thread
    size_t woff[2]; int wsf[2];
#pragma unroll
    for (int i = 0; i < 2; i++) {
        int idx = tid + i * GT, row = idx >> 2, ch = idx & 3;
        woff[i] = (size_t)(n0 + row) * D_SZ + ch * 8;
        wsf[i]  = row * ROWB + ch * 16;
    }

    auto issueW = [&](int c, int buf) {
        const uint32_t s0 = sb + buf * STAGE;
        const size_t ka = (size_t)c * KC;
#pragma unroll
        for (int i = 0; i < 2; i++) {
            CP_ASYNC16(s0 + OFF_WHI + wsf[i], g_Whi + woff[i] + ka);
            CP_ASYNC16(s0 + OFF_WLO + wsf[i], g_Wlo + woff[i] + ka);
        }
        CP_COMMIT();
    };
    float4 vA[2];
    auto ldA = [&](int c) {
        const size_t ka = (size_t)c * KC;
#pragma unroll
        for (int i = 0; i < 2; i++)
            vA[i] = *(const float4*)(nf + aoff[i] + ka);
    };
    auto stA = [&](int buf) {
        char* sp = smg + buf * STAGE;
#pragma unroll
        for (int i = 0; i < 2; i++) {
            float4 v = vA[i];
            __half h0 = __float2half_rn(v.x), h1 = __float2half_rn(v.y);
            __half h2 = __float2half_rn(v.z), h3 = __float2half_rn(v.w);
            __half l0 = __float2half_rn(v.x - __half2float(h0));
            __half l1 = __float2half_rn(v.y - __half2float(h1));
            __half l2 = __float2half_rn(v.z - __half2float(h2));
            __half l3 = __float2half_rn(v.w - __half2float(h3));
            __half2 hv[2] = { __halves2half2(h0, h1), __halves2half2(h2, h3) };
            __half2 lv[2] = { __halves2half2(l0, l1), __halves2half2(l2, l3) };
            *(uint2*)(sp + OFF_AHI + asf[i]) = *(uint2*)hv;
            *(uint2*)(sp + OFF_ALO + asf[i]) = *(uint2*)lv;
        }
    };

    // prologue
    ldA(0);
    issueW(0, 0);
    stA(0);

    const int g = lane >> 3, r = lane & 7;
    const int arow = wm * 32 + ((g & 1) << 3) + r;       // + mt*16
    const int brow = wn * 64 + ((g >> 1) << 3) + r;      // + bt*16
    const int akc  = (g >> 1);
    const int bkc  = (g & 1);

    for (int c = 0; c < NCHUNK; c++) {
        const int buf = c & 1;
        if (c + 1 < NCHUNK) {
            ldA(c + 1);
            issueW(c + 1, buf ^ 1);
            CP_WAIT1();
        } else {
            CP_WAIT0();
        }
        __syncthreads();

        const uint32_t abase = sb + buf * STAGE;
#pragma unroll
        for (int ks = 0; ks < 2; ks++) {
            uint32_t ah[2][4], al[2][4];
#pragma unroll
            for (int mt = 0; mt < 2; mt++) {
                uint32_t ad = abase + OFF_AHI + (arow + mt * 16) * ROWB
                            + (ks * 2 + akc) * 16;
                LDSM4(ah[mt], ad);
                LDSM4(al[mt], ad + (OFF_ALO - OFF_AHI));
            }
#pragma unroll
            for (int bt = 0; bt < 4; bt++) {
                uint32_t bh[4], bl[4];
                uint32_t bd = abase + OFF_WHI + (brow + bt * 16) * ROWB
                            + (ks * 2 + bkc) * 16;
                LDSM4(bh, bd);
                LDSM4(bl, bd + (OFF_WLO - OFF_WHI));
#pragma unroll
                for (int mt = 0; mt < 2; mt++)
#pragma unroll
                    for (int hh = 0; hh < 2; hh++) {
                        const int nt = bt * 2 + hh;
                        MMA_16816(acc[mt][nt], ah[mt], &bh[hh * 2]);
                        MMA_16816(acc[mt][nt], ah[mt], &bl[hh * 2]);
                        MMA_16816(acc[mt][nt], al[mt], &bh[hh * 2]);
                    }
            }
        }

        if (c + 1 < NCHUNK)
            stA(buf ^ 1);
        __syncthreads();
    }

    // epilogue: compact-row store, predicated on Mc
    const int er = lane >> 2, ec = (lane & 3) * 2;
#pragma unroll
    for (int mt = 0; mt < 2; mt++) {
        const int row = m0 + wm * 32 + mt * 16 + er;
#pragma unroll
        for (int nt = 0; nt < 8; nt++) {
            const int col = n0 + wn * 64 + nt * 8 + ec;
            if (row < Mc)
                *(float2*)&g_att[(size_t)row * D_SZ + col] =
                    make_float2(acc[mt][nt][0], acc[mt][nt][1]);
            if (row + 8 < Mc)
                *(float2*)&g_att[(size_t)(row + 8) * D_SZ + col] =
                    make_float2(acc[mt][nt][2], acc[mt][nt][3]);
        }
    }
}

// ---------------------------------------------------------------------------
// Band + softmax: one warp handles FOUR adjacent j rows (unchanged).
// ---------------------------------------------------------------------------
#define NJ 4
#define UNION_W (WPAST + WFUT + NJ)   // 24

__global__ __launch_bounds__(256) void edgeatt_band_softmax(
    const float* __restrict__ nf,     // [B, L, 512]
    const int*   __restrict__ tlen,   // [B]
    float*       __restrict__ out)    // [B, L, 110]
{
    const int b    = blockIdx.y;
    const int warp = threadIdx.x >> 5;
    const int lane = threadIdx.x & 31;
    const int j0   = blockIdx.x * (8 * NJ) + warp * NJ;
    if (j0 >= L_SZ) return;

    const int len  = tlen[b];
    const int base = g_cbase[b];

    if (j0 >= len) {
#pragma unroll
        for (int r = 0; r < NJ; r++) {
            int j = j0 + r;
            if (j >= L_SZ) break;
            float* orow = out + ((size_t)b * L_SZ + j) * 110;
#pragma unroll
            for (int c0 = 0; c0 < 128; c0 += 32) {
                int c = c0 + lane;
                if (c < 110) orow[c] = 0.f;
            }
        }
        return;
    }

    float4 x[NJ][4];
#pragma unroll
    for (int r = 0; r < NJ; r++) {
        int j = min(j0 + r, L_SZ - 1);
        const float* xr = nf + ((size_t)b * L_SZ + j) * D_SZ;
#pragma unroll
        for (int q = 0; q < 4; q++)
            x[r][q] = *(const float4*)&xr[lane * 16 + q * 4];
    }

    const int lo = j0 - WPAST;
    float sc[NJ] = {0.f, 0.f, 0.f, 0.f};

#pragma unroll 1
    for (int wi = 0; wi < UNION_W; wi++) {
        int l = lo + wi;
        if (l < 0 || l >= len) continue;
        const float* ar = g_att + ((size_t)(base + l)) * D_SZ;
        float s0 = 0.f, s1 = 0.f, s2 = 0.f, s3 = 0.f;
#pragma unroll
        for (int q = 0; q < 4; q++) {
            float4 av = *(const float4*)&ar[lane * 16 + q * 4];
            s0 = fmaf(av.x, x[0][q].x, s0); s1 = fmaf(av.x, x[1][q].x, s1);
            s2 = fmaf(av.x, x[2][q].x, s2); s3 = fmaf(av.x, x[3][q].x, s3);
            s0 = fmaf(av.y, x[0][q].y, s0); s1 = fmaf(av.y, x[1][q].y, s1);
            s2 = fmaf(av.y, x[2][q].y, s2); s3 = fmaf(av.y, x[3][q].y, s3);
            s0 = fmaf(av.z, x[0][q].z, s0); s1 = fmaf(av.z, x[1][q].z, s1);
            s2 = fmaf(av.z, x[2][q].z, s2); s3 = fmaf(av.z, x[3][q].z, s3);
            s0 = fmaf(av.w, x[0][q].w, s0); s1 = fmaf(av.w, x[1][q].w, s1);
            s2 = fmaf(av.w, x[2][q].w, s2); s3 = fmaf(av.w, x[3][q].w, s3);
        }
#pragma unroll
        for (int off = 16; off > 0; off >>= 1) {
            s0 += __shfl_xor_sync(0xffffffffu, s0, off);
            s1 += __shfl_xor_sync(0xffffffffu, s1, off);
            s2 += __shfl_xor_sync(0xffffffffu, s2, off);
            s3 += __shfl_xor_sync(0xffffffffu, s3, off);
        }
        if (lane == wi)     sc[0] = s0;
        if (lane == wi - 1) sc[1] = s1;
        if (lane == wi - 2) sc[2] = s2;
        if (lane == wi - 3) sc[3] = s3;
    }

    float pr[NJ];
#pragma unroll
    for (int r = 0; r < NJ; r++) {
        int  j  = j0 + r;
        int  lw = lo + r + lane;
        bool va = (lane < 21) && (lw >= 0) && (lw < len) && (j < len) && (j < L_SZ);
        float v = va ? sc[r] : -1e30f;
        float m = v;
#pragma unroll
        for (int off = 16; off > 0; off >>= 1)
            m = fmaxf(m, __shfl_xor_sync(0xffffffffu, m, off));
        float p = va ? expf(v - m) : 0.f;
        float t = p;
#pragma unroll
        for (int off = 16; off > 0; off >>= 1)
            t += __shfl_xor_sync(0xffffffffu, t, off);
        pr[r] = va ? (p / t) : 0.f;
    }

#pragma unroll
    for (int r = 0; r < NJ; r++) {
        int j = j0 + r;
        if (j >= L_SZ) break;
        float* orow = out + ((size_t)b * L_SZ + j) * 110;
#pragma unroll
        for (int c0 = 0; c0 < 128; c0 += 32) {
            int c  = c0 + lane;
            int w  = c - lo - r;
            int si = (w >= 0 && w < 32) ? w : 31;
            float val = __shfl_sync(0xffffffffu, pr[r], si);
            if (w < 0 || w >= 32) val = 0.f;
            if (c < 110) orow[c] = val;
        }
    }
}

// ---------------------------------------------------------------------------
extern "C" void kernel_launch(void* const* d_in, const int* in_sizes, int n_in,
                              void* d_out, int out_size)
{
    const float* nf   = (const float*)d_in[0];
    const float* W    = (const float*)d_in[1];
    const int*   tlen = (const int*)d_in[2];
    float* out = (float*)d_out;

    static int attr_done = 0;
    if (!attr_done) {
        cudaFuncSetAttribute(edgeatt_gemm_hmma,
                             cudaFuncAttributeMaxDynamicSharedMemorySize, GEMM_SMEM);
        attr_done = 1;
    }

    scan_len<<<1, 1024>>>(tlen);
    fill_rowmap<<<B_SZ, 128>>>(tlen);
    split_W<<<(D_SZ * D_SZ / 4 + 255) / 256, 256>>>(W);

    dim3 gg(D_SZ / 256, M_TOT / 128);    // (2, 880); dead tiles exit on Mc
    edgeatt_gemm_hmma<<<gg, GT, GEMM_SMEM>>>(nf);

    dim3 gb((L_SZ + 8 * NJ - 1) / (8 * NJ), B_SZ);   // (4, 1024)
    edgeatt_band_softmax<<<gb, 256>>>(nf, tlen, out);
}